// round 5
// baseline (speedup 1.0000x reference)
#include <cuda_runtime.h>

// ============================================================================
// SGNN: out = relu( 0.5*(softmax(p p^T) @ x + x) @ W3^T + b3 )
// where p = x @ (W2 W1)^T + (W2 b1 + b2).
//
// Key simplification: softmax rows sum to 1, R = softmax + I => rowsum(R)=2
// => D^{-1/2} R D^{-1/2} = R/2 exactly (to fp32 rounding ~1e-7). So the
// 4096x4096 adjacency is never materialized: flash-attention streaming
// softmax with Q=K=p, V=x, residual 0.5*x, fused output projection + relu.
// ============================================================================

#define LDT 68   // padded smem row stride (floats): float4-aligned, kills bank conflicts

static constexpr int BATCH = 4;
static constexpr int NTOK  = 4096;
static constexpr int FDIM  = 64;

// Scratch (device globals: alloc-free, graph-capture safe)
__device__ float g_p[BATCH * NTOK * FDIM];   // 4 MB, stays in L2
__device__ float g_Weff[FDIM * FDIM];
__device__ float g_beff[FDIM];

// ----------------------------------------------------------------------------
// Tile loaders: 64x64 fp32 tile, 256 threads, fully coalesced float4 gmem reads
// ----------------------------------------------------------------------------

// s[k][n] = g[n][k]  (transposed store, padded stride LDT)
__device__ __forceinline__ void load_tile_T(const float* __restrict__ g,
                                            float* __restrict__ s) {
    int t = threadIdx.x;
#pragma unroll
    for (int i = 0; i < 4; i++) {
        int idx = t + i * 256;          // 0..1023 float4 units
        int n   = idx >> 4;             // row 0..63
        int k4  = (idx & 15) << 2;      // col 0,4,..,60
        float4 v = *reinterpret_cast<const float4*>(g + n * 64 + k4);
        s[(k4 + 0) * LDT + n] = v.x;
        s[(k4 + 1) * LDT + n] = v.y;
        s[(k4 + 2) * LDT + n] = v.z;
        s[(k4 + 3) * LDT + n] = v.w;
    }
}

// s[n][k] = g[n][k]  (row-major, padded stride LDT)
__device__ __forceinline__ void load_tile_N(const float* __restrict__ g,
                                            float* __restrict__ s) {
    int t = threadIdx.x;
#pragma unroll
    for (int i = 0; i < 4; i++) {
        int idx = t + i * 256;
        int n   = idx >> 4;
        int k4  = (idx & 15) << 2;
        *reinterpret_cast<float4*>(s + n * LDT + k4) =
            *reinterpret_cast<const float4*>(g + n * 64 + k4);
    }
}

// ----------------------------------------------------------------------------
// Kernel 1: W_eff = W2 @ W1, b_eff = W2 @ b1 + b2   (tiny, one block)
// ----------------------------------------------------------------------------
__global__ __launch_bounds__(256) void prep_kernel(
    const float* __restrict__ W1, const float* __restrict__ b1,
    const float* __restrict__ W2, const float* __restrict__ b2) {
    __shared__ float s1[64 * 64];
    __shared__ float s2[64 * 64];
    int t = threadIdx.x;
    for (int i = t; i < 4096; i += 256) { s1[i] = W1[i]; s2[i] = W2[i]; }
    __syncthreads();
    for (int e = t; e < 4096; e += 256) {
        int i = e >> 6, j = e & 63;
        float acc = 0.f;
#pragma unroll 8
        for (int k = 0; k < 64; k++) acc = fmaf(s2[i * 64 + k], s1[k * 64 + j], acc);
        g_Weff[e] = acc;
    }
    if (t < 64) {
        float acc = b2[t];
#pragma unroll 8
        for (int k = 0; k < 64; k++) acc = fmaf(s2[t * 64 + k], b1[k], acc);
        g_beff[t] = acc;
    }
}

// ----------------------------------------------------------------------------
// Kernel 2: p = x @ W_eff^T + b_eff   ([16384, 64], 64-row tiles, 4x4 microtile)
// ----------------------------------------------------------------------------
__global__ __launch_bounds__(256) void p_kernel(const float* __restrict__ x) {
    __shared__ float sXT[64 * LDT];   // sXT[j][n] = x[n][j]
    __shared__ float sWT[64 * LDT];   // sWT[j][i] = Weff[i][j]
    int n0 = blockIdx.x * 64;
    load_tile_T(x + (size_t)n0 * 64, sXT);
    load_tile_T(g_Weff, sWT);
    __syncthreads();

    int t = threadIdx.x;
    int ty = t >> 4, tx = t & 15;
    float acc[4][4] = {};
#pragma unroll 16
    for (int j = 0; j < 64; j++) {
        float4 a = *reinterpret_cast<float4*>(&sXT[j * LDT + 4 * ty]);
        float4 b = *reinterpret_cast<float4*>(&sWT[j * LDT + 4 * tx]);
        float av[4] = {a.x, a.y, a.z, a.w};
        float bv[4] = {b.x, b.y, b.z, b.w};
#pragma unroll
        for (int r = 0; r < 4; r++)
#pragma unroll
            for (int c = 0; c < 4; c++) acc[r][c] = fmaf(av[r], bv[c], acc[r][c]);
    }
    float bb[4];
#pragma unroll
    for (int c = 0; c < 4; c++) bb[c] = g_beff[4 * tx + c];
#pragma unroll
    for (int r = 0; r < 4; r++) {
        float4 o = make_float4(acc[r][0] + bb[0], acc[r][1] + bb[1],
                               acc[r][2] + bb[2], acc[r][3] + bb[3]);
        *reinterpret_cast<float4*>(&g_p[(size_t)(n0 + 4 * ty + r) * 64 + 4 * tx]) = o;
    }
}

// ----------------------------------------------------------------------------
// Kernel 3: flash attention + residual + output projection + relu (fused)
// grid = (64 row-blocks, 4 batches), 256 threads, 4x4 microtiles.
// Online softmax stats replicated across the 16 lanes sharing a row group
// via xor-shuffles (offsets 1,2,4,8 stay within the 16-lane group).
// ----------------------------------------------------------------------------
__global__ __launch_bounds__(256) void flash_kernel(
    const float* __restrict__ x, const float* __restrict__ W3,
    const float* __restrict__ b3, float* __restrict__ out) {
    extern __shared__ float smem[];
    float* sQT = smem;                  // [64][LDT]  Q^T (p rows m0..m0+63)
    float* sKT = sQT + 64 * LDT;        // [64][LDT]  K^T tile ; W3^T in epilogue
    float* sV  = sKT + 64 * LDT;        // [64][LDT]  V tile (x rows, row-major)
    float* sPT = sV  + 64 * LDT;        // [64][LDT]  P^T tile ; Z^T in epilogue

    int batch = blockIdx.y;
    int m0    = blockIdx.x * 64;
    const float* pb = g_p + (size_t)batch * NTOK * 64;
    const float* xb = x   + (size_t)batch * NTOK * 64;

    load_tile_T(pb + (size_t)m0 * 64, sQT);

    int t  = threadIdx.x;
    int ty = t >> 4, tx = t & 15;
    const float* qbase = sQT + 4 * ty;
    const float* kbase = sKT + 4 * tx;
    const float* pbase = sPT + 4 * ty;
    const float* vbase = sV  + 4 * tx;

    float O[4][4] = {};
    float m[4] = {-1e30f, -1e30f, -1e30f, -1e30f};
    float l[4] = {};

    for (int j0 = 0; j0 < NTOK; j0 += 64) {
        __syncthreads();                                  // prev GEMM2 done
        load_tile_T(pb + (size_t)j0 * 64, sKT);
        load_tile_N(xb + (size_t)j0 * 64, sV);
        __syncthreads();

        // --- GEMM1: S = Q K^T (64x64 tile, raw logits) ---
        float S[4][4] = {};
#pragma unroll 16
        for (int k = 0; k < 64; k++) {
            float4 q  = *reinterpret_cast<const float4*>(qbase + k * LDT);
            float4 kk = *reinterpret_cast<const float4*>(kbase + k * LDT);
            float qv[4] = {q.x, q.y, q.z, q.w};
            float kv[4] = {kk.x, kk.y, kk.z, kk.w};
#pragma unroll
            for (int r = 0; r < 4; r++)
#pragma unroll
                for (int c = 0; c < 4; c++) S[r][c] = fmaf(qv[r], kv[c], S[r][c]);
        }

        // --- online softmax (per row; stats replicated across 16 tx lanes) ---
#pragma unroll
        for (int r = 0; r < 4; r++) {
            float mx = fmaxf(fmaxf(S[r][0], S[r][1]), fmaxf(S[r][2], S[r][3]));
#pragma unroll
            for (int off = 8; off; off >>= 1)
                mx = fmaxf(mx, __shfl_xor_sync(0xffffffffu, mx, off));
            float mn   = fmaxf(m[r], mx);
            float corr = __expf(m[r] - mn);
            m[r] = mn;
            float rs = 0.f;
#pragma unroll
            for (int c = 0; c < 4; c++) { S[r][c] = __expf(S[r][c] - mn); rs += S[r][c]; }
#pragma unroll
            for (int off = 8; off; off >>= 1)
                rs += __shfl_xor_sync(0xffffffffu, rs, off);
            l[r] = l[r] * corr + rs;
#pragma unroll
            for (int f = 0; f < 4; f++) O[r][f] *= corr;
        }

        // --- store P transposed: sPT[key][row] ---
#pragma unroll
        for (int c = 0; c < 4; c++) {
            float4 pv = make_float4(S[0][c], S[1][c], S[2][c], S[3][c]);
            *reinterpret_cast<float4*>(&sPT[(4 * tx + c) * LDT + 4 * ty]) = pv;
        }
        __syncthreads();

        // --- GEMM2: O += P V ---
#pragma unroll 16
        for (int j = 0; j < 64; j++) {
            float4 pp = *reinterpret_cast<const float4*>(pbase + j * LDT);
            float4 vv = *reinterpret_cast<const float4*>(vbase + j * LDT);
            float pr[4] = {pp.x, pp.y, pp.z, pp.w};
            float vf[4] = {vv.x, vv.y, vv.z, vv.w};
#pragma unroll
            for (int r = 0; r < 4; r++)
#pragma unroll
                for (int f = 0; f < 4; f++) O[r][f] = fmaf(pr[r], vf[f], O[r][f]);
        }
    }

    // ========================= epilogue =========================
    __syncthreads();
    load_tile_T(W3, sKT);   // sKT[f][o] = W3[o][f]

    // z = 0.5*(O/l + x_row)
    float z[4][4];
#pragma unroll
    for (int r = 0; r < 4; r++) {
        float inv = 0.5f / l[r];
        float4 xv = *reinterpret_cast<const float4*>(
            &xb[(size_t)(m0 + 4 * ty + r) * 64 + 4 * tx]);
        z[r][0] = O[r][0] * inv + 0.5f * xv.x;
        z[r][1] = O[r][1] * inv + 0.5f * xv.y;
        z[r][2] = O[r][2] * inv + 0.5f * xv.z;
        z[r][3] = O[r][3] * inv + 0.5f * xv.w;
    }
    // store Z transposed into sPT: sZT[f][row]
#pragma unroll
    for (int f = 0; f < 4; f++) {
        float4 zv = make_float4(z[0][f], z[1][f], z[2][f], z[3][f]);
        *reinterpret_cast<float4*>(&sPT[(4 * tx + f) * LDT + 4 * ty]) = zv;
    }
    __syncthreads();

    // out = relu(Z @ W3^T + b3)
    float acc[4][4] = {};
#pragma unroll 16
    for (int f = 0; f < 64; f++) {
        float4 zz = *reinterpret_cast<const float4*>(pbase + f * LDT);
        float4 ww = *reinterpret_cast<const float4*>(kbase + f * LDT);
        float zr[4] = {zz.x, zz.y, zz.z, zz.w};
        float wo[4] = {ww.x, ww.y, ww.z, ww.w};
#pragma unroll
        for (int r = 0; r < 4; r++)
#pragma unroll
            for (int o = 0; o < 4; o++) acc[r][o] = fmaf(zr[r], wo[o], acc[r][o]);
    }
    float bb[4];
#pragma unroll
    for (int o = 0; o < 4; o++) bb[o] = __ldg(&b3[4 * tx + o]);
#pragma unroll
    for (int r = 0; r < 4; r++) {
        float4 res = make_float4(fmaxf(acc[r][0] + bb[0], 0.f),
                                 fmaxf(acc[r][1] + bb[1], 0.f),
                                 fmaxf(acc[r][2] + bb[2], 0.f),
                                 fmaxf(acc[r][3] + bb[3], 0.f));
        *reinterpret_cast<float4*>(
            &out[((size_t)batch * NTOK + m0 + 4 * ty + r) * 64 + 4 * tx]) = res;
    }
}

// ----------------------------------------------------------------------------
extern "C" void kernel_launch(void* const* d_in, const int* in_sizes, int n_in,
                              void* d_out, int out_size) {
    (void)in_sizes; (void)n_in; (void)out_size;
    const float* x  = (const float*)d_in[0];
    const float* W1 = (const float*)d_in[1];
    const float* b1 = (const float*)d_in[2];
    const float* W2 = (const float*)d_in[3];
    const float* b2 = (const float*)d_in[4];
    const float* W3 = (const float*)d_in[5];
    const float* b3 = (const float*)d_in[6];
    float* out = (float*)d_out;

    constexpr int FLASH_SMEM = 4 * 64 * LDT * (int)sizeof(float);  // 69632 B
    cudaFuncSetAttribute(flash_kernel,
                         cudaFuncAttributeMaxDynamicSharedMemorySize, FLASH_SMEM);

    prep_kernel<<<1, 256>>>(W1, b1, W2, b2);
    p_kernel<<<BATCH * NTOK / 64, 256>>>(x);
    flash_kernel<<<dim3(NTOK / 64, BATCH), 256, FLASH_SMEM>>>(x, W3, b3, out);
}

// round 7
// speedup vs baseline: 1.0798x; 1.0798x over previous
#include <cuda_runtime.h>

// ============================================================================
// SGNN: out = relu( 0.5*(softmax(p p^T) @ x + x) @ W3^T + b3 )
// where p = x @ (W2 W1)^T + (W2 b1 + b2).
//
// softmax rows sum to 1, R = softmax + I => rowsum(R)=2 => D^{-1/2} R D^{-1/2}
// = R/2 exactly. Flash-attention streaming softmax (Q=K=p, V=x), residual
// 0.5*x, fused output projection + relu. The 4096x4096 adjacency is never
// materialized.
//
// R6: fix the mangled FFMA2 statement in p_kernel's W_eff loop (row 3 was
// computing aw += aw*aw). Everything else identical to R5.
// ============================================================================

#define LDT 68   // padded smem row stride (floats)

static constexpr int BATCH = 4;
static constexpr int NTOK  = 4096;
static constexpr int FDIM  = 64;

__device__ float g_p[BATCH * NTOK * FDIM];   // 4 MB scratch, L2-resident

using u64 = unsigned long long;

// ---- packed f32x2 helpers --------------------------------------------------
__device__ __forceinline__ u64 pk2(float x, float y) {
    u64 r; asm("mov.b64 %0, {%1, %2};" : "=l"(r) : "f"(x), "f"(y)); return r;
}
__device__ __forceinline__ u64 dup2(float x) {
    u64 r; asm("mov.b64 %0, {%1, %1};" : "=l"(r) : "f"(x)); return r;
}
__device__ __forceinline__ void fma2(u64& d, u64 a, u64 b) {
    asm("fma.rn.f32x2 %0, %1, %2, %0;" : "+l"(d) : "l"(a), "l"(b));
}
__device__ __forceinline__ void mul2(u64& d, u64 a) {
    asm("mul.rn.f32x2 %0, %0, %1;" : "+l"(d) : "l"(a));
}
__device__ __forceinline__ float2 up2(u64 v) {
    float2 f; asm("mov.b64 {%0, %1}, %2;" : "=f"(f.x), "=f"(f.y) : "l"(v)); return f;
}

// ---- tile loaders: 64x64 fp32, 256 threads, coalesced float4 ---------------
// s[k][n] = g[n][k]
__device__ __forceinline__ void load_tile_T(const float* __restrict__ g,
                                            float* __restrict__ s) {
    int t = threadIdx.x;
#pragma unroll
    for (int i = 0; i < 4; i++) {
        int idx = t + i * 256;
        int n   = idx >> 4;
        int k4  = (idx & 15) << 2;
        float4 v = *reinterpret_cast<const float4*>(g + n * 64 + k4);
        s[(k4 + 0) * LDT + n] = v.x;
        s[(k4 + 1) * LDT + n] = v.y;
        s[(k4 + 2) * LDT + n] = v.z;
        s[(k4 + 3) * LDT + n] = v.w;
    }
}
// s[n][k] = g[n][k]
__device__ __forceinline__ void load_tile_N(const float* __restrict__ g,
                                            float* __restrict__ s) {
    int t = threadIdx.x;
#pragma unroll
    for (int i = 0; i < 4; i++) {
        int idx = t + i * 256;
        int n   = idx >> 4;
        int k4  = (idx & 15) << 2;
        *reinterpret_cast<float4*>(s + n * LDT + k4) =
            *reinterpret_cast<const float4*>(g + n * 64 + k4);
    }
}

// ----------------------------------------------------------------------------
// Kernel 1: fused  W_eff = W2@W1, b_eff = W2@b1+b2  (redundant per block) then
// p = x @ W_eff^T + b_eff.   grid = 256, block = 256, 4x4 microtile
// ----------------------------------------------------------------------------
__global__ __launch_bounds__(256) void p_kernel(
    const float* __restrict__ x,
    const float* __restrict__ W1, const float* __restrict__ b1,
    const float* __restrict__ W2, const float* __restrict__ b2) {
    extern __shared__ float smem[];
    float* sXT  = smem;                 // [64][LDT]  x^T tile
    float* sWT  = sXT  + 64 * LDT;      // [64][LDT]  sWT[j][i] = Weff[i][j]
    float* sW1  = sWT  + 64 * LDT;      // [64][LDT]  W1 row-major
    float* sW2T = sW1  + 64 * LDT;      // [64][LDT]  sW2T[k][i] = W2[i][k]
    float* sB1  = sW2T + 64 * LDT;      // [64]

    int n0 = blockIdx.x * 64;
    load_tile_T(x + (size_t)n0 * 64, sXT);
    load_tile_N(W1, sW1);
    load_tile_T(W2, sW2T);
    int t = threadIdx.x;
    if (t < 64) sB1[t] = b1[t];
    __syncthreads();

    int ty = t >> 4, tx = t & 15;

    // Weff[i][j] = sum_k W2[i][k] W1[k][j]; this thread: i = 4tx.., j = 4ty..
    u64 aw[4][2] = {};
#pragma unroll 16
    for (int k = 0; k < 64; k++) {
        float4 a = *reinterpret_cast<float4*>(&sW2T[k * LDT + 4 * tx]); // over i
        float4 b = *reinterpret_cast<float4*>(&sW1 [k * LDT + 4 * ty]); // over j
        u64 a01 = pk2(a.x, a.y), a23 = pk2(a.z, a.w);
        u64 d;
        d = dup2(b.x); fma2(aw[0][0], a01, d); fma2(aw[0][1], a23, d);
        d = dup2(b.y); fma2(aw[1][0], a01, d); fma2(aw[1][1], a23, d);
        d = dup2(b.z); fma2(aw[2][0], a01, d); fma2(aw[2][1], a23, d);
        d = dup2(b.w); fma2(aw[3][0], a01, d); fma2(aw[3][1], a23, d);
    }
    // b_eff for i = 4tx..4tx+3 (replicated across ty)
    float be[4];
    {
        float4 bv = *reinterpret_cast<const float4*>(&b2[4 * tx]);
        be[0] = bv.x; be[1] = bv.y; be[2] = bv.z; be[3] = bv.w;
#pragma unroll 16
        for (int k = 0; k < 64; k++) {
            float4 w = *reinterpret_cast<float4*>(&sW2T[k * LDT + 4 * tx]);
            float bk = sB1[k];
            be[0] = fmaf(w.x, bk, be[0]); be[1] = fmaf(w.y, bk, be[1]);
            be[2] = fmaf(w.z, bk, be[2]); be[3] = fmaf(w.w, bk, be[3]);
        }
    }
    // aw[jj] holds Weff[4tx+0..3][4ty+jj]  ->  sWT[j][i] = Weff[i][j]
#pragma unroll
    for (int jj = 0; jj < 4; jj++) {
        float2 lo = up2(aw[jj][0]), hi = up2(aw[jj][1]);
        float4 o = make_float4(lo.x, lo.y, hi.x, hi.y);
        *reinterpret_cast<float4*>(&sWT[(4 * ty + jj) * LDT + 4 * tx]) = o;
    }
    __syncthreads();

    // p = x @ Weff^T + b_eff
    u64 acc[4][2] = {};
#pragma unroll 16
    for (int j = 0; j < 64; j++) {
        float4 a = *reinterpret_cast<float4*>(&sXT[j * LDT + 4 * ty]);
        float4 b = *reinterpret_cast<float4*>(&sWT[j * LDT + 4 * tx]);
        u64 b01 = pk2(b.x, b.y), b23 = pk2(b.z, b.w);
        u64 d;
        d = dup2(a.x); fma2(acc[0][0], d, b01); fma2(acc[0][1], d, b23);
        d = dup2(a.y); fma2(acc[1][0], d, b01); fma2(acc[1][1], d, b23);
        d = dup2(a.z); fma2(acc[2][0], d, b01); fma2(acc[2][1], d, b23);
        d = dup2(a.w); fma2(acc[3][0], d, b01); fma2(acc[3][1], d, b23);
    }
#pragma unroll
    for (int r = 0; r < 4; r++) {
        float2 lo = up2(acc[r][0]), hi = up2(acc[r][1]);
        float4 o = make_float4(lo.x + be[0], lo.y + be[1],
                               hi.x + be[2], hi.y + be[3]);
        *reinterpret_cast<float4*>(
            &g_p[(size_t)(n0 + 4 * ty + r) * 64 + 4 * tx]) = o;
    }
}

// ----------------------------------------------------------------------------
// Kernel 2: flash attention + residual + projection + relu
// grid = (64, 4), 256 threads, 4x4 microtiles, FFMA2 inner loops
// ----------------------------------------------------------------------------
__global__ __launch_bounds__(256) void flash_kernel(
    const float* __restrict__ x, const float* __restrict__ W3,
    const float* __restrict__ b3, float* __restrict__ out) {
    extern __shared__ float smem[];
    float* sQT = smem;                  // [64][LDT]  Q^T
    float* sKT = sQT + 64 * LDT;        // [64][LDT]  K^T ; W3^T in epilogue
    float* sV  = sKT + 64 * LDT;        // [64][LDT]  V row-major
    float* sPT = sV  + 64 * LDT;        // [64][LDT]  P^T ; Z^T in epilogue

    int batch = blockIdx.y;
    int m0    = blockIdx.x * 64;
    const float* pb = g_p + (size_t)batch * NTOK * 64;
    const float* xb = x   + (size_t)batch * NTOK * 64;

    load_tile_T(pb + (size_t)m0 * 64, sQT);

    int t  = threadIdx.x;
    int ty = t >> 4, tx = t & 15;
    const float* qbase = sQT + 4 * ty;
    const float* kbase = sKT + 4 * tx;
    const float* pbase = sPT + 4 * ty;
    const float* vbase = sV  + 4 * tx;

    u64   Op[4][2] = {};                      // O accumulators, packed pairs
    float m[4] = {-1e30f, -1e30f, -1e30f, -1e30f};
    float l[4] = {};

    for (int j0 = 0; j0 < NTOK; j0 += 64) {
        __syncthreads();
        load_tile_T(pb + (size_t)j0 * 64, sKT);
        load_tile_N(xb + (size_t)j0 * 64, sV);
        __syncthreads();

        // --- GEMM1: S = Q K^T ---
        u64 Sp[4][2] = {};
#pragma unroll 16
        for (int k = 0; k < 64; k++) {
            float4 q  = *reinterpret_cast<const float4*>(qbase + k * LDT);
            float4 kk = *reinterpret_cast<const float4*>(kbase + k * LDT);
            u64 b01 = pk2(kk.x, kk.y), b23 = pk2(kk.z, kk.w);
            u64 d;
            d = dup2(q.x); fma2(Sp[0][0], d, b01); fma2(Sp[0][1], d, b23);
            d = dup2(q.y); fma2(Sp[1][0], d, b01); fma2(Sp[1][1], d, b23);
            d = dup2(q.z); fma2(Sp[2][0], d, b01); fma2(Sp[2][1], d, b23);
            d = dup2(q.w); fma2(Sp[3][0], d, b01); fma2(Sp[3][1], d, b23);
        }
        float S[4][4];
#pragma unroll
        for (int r = 0; r < 4; r++) {
            float2 lo = up2(Sp[r][0]), hi = up2(Sp[r][1]);
            S[r][0] = lo.x; S[r][1] = lo.y; S[r][2] = hi.x; S[r][3] = hi.y;
        }

        // --- online softmax (stats replicated across the 16 tx lanes) ---
#pragma unroll
        for (int r = 0; r < 4; r++) {
            float mx = fmaxf(fmaxf(S[r][0], S[r][1]), fmaxf(S[r][2], S[r][3]));
#pragma unroll
            for (int off = 8; off; off >>= 1)
                mx = fmaxf(mx, __shfl_xor_sync(0xffffffffu, mx, off));
            float mn   = fmaxf(m[r], mx);
            float corr = __expf(m[r] - mn);
            m[r] = mn;
            float rs = 0.f;
#pragma unroll
            for (int c = 0; c < 4; c++) { S[r][c] = __expf(S[r][c] - mn); rs += S[r][c]; }
#pragma unroll
            for (int off = 8; off; off >>= 1)
                rs += __shfl_xor_sync(0xffffffffu, rs, off);
            l[r] = l[r] * corr + rs;
            u64 c2 = dup2(corr);
            mul2(Op[r][0], c2); mul2(Op[r][1], c2);
        }

        // --- store P transposed: sPT[key][row] ---
#pragma unroll
        for (int c = 0; c < 4; c++) {
            float4 pv = make_float4(S[0][c], S[1][c], S[2][c], S[3][c]);
            *reinterpret_cast<float4*>(&sPT[(4 * tx + c) * LDT + 4 * ty]) = pv;
        }
        __syncthreads();

        // --- GEMM2: O += P V ---
#pragma unroll 16
        for (int j = 0; j < 64; j++) {
            float4 pp = *reinterpret_cast<const float4*>(pbase + j * LDT);
            float4 vv = *reinterpret_cast<const float4*>(vbase + j * LDT);
            u64 b01 = pk2(vv.x, vv.y), b23 = pk2(vv.z, vv.w);
            u64 d;
            d = dup2(pp.x); fma2(Op[0][0], d, b01); fma2(Op[0][1], d, b23);
            d = dup2(pp.y); fma2(Op[1][0], d, b01); fma2(Op[1][1], d, b23);
            d = dup2(pp.z); fma2(Op[2][0], d, b01); fma2(Op[2][1], d, b23);
            d = dup2(pp.w); fma2(Op[3][0], d, b01); fma2(Op[3][1], d, b23);
        }
    }

    // ========================= epilogue =========================
    __syncthreads();
    load_tile_T(W3, sKT);   // sKT[f][o] = W3[o][f]

    // z = 0.5*(O/l + x_row), stored transposed into sPT
    float z[4][4];
#pragma unroll
    for (int r = 0; r < 4; r++) {
        float inv = 0.5f / l[r];
        float4 xv = *reinterpret_cast<const float4*>(
            &xb[(size_t)(m0 + 4 * ty + r) * 64 + 4 * tx]);
        float2 lo = up2(Op[r][0]), hi = up2(Op[r][1]);
        z[r][0] = lo.x * inv + 0.5f * xv.x;
        z[r][1] = lo.y * inv + 0.5f * xv.y;
        z[r][2] = hi.x * inv + 0.5f * xv.z;
        z[r][3] = hi.y * inv + 0.5f * xv.w;
    }
#pragma unroll
    for (int f = 0; f < 4; f++) {
        float4 zv = make_float4(z[0][f], z[1][f], z[2][f], z[3][f]);
        *reinterpret_cast<float4*>(&sPT[(4 * tx + f) * LDT + 4 * ty]) = zv;
    }
    __syncthreads();

    // out = relu(Z @ W3^T + b3)
    u64 acc[4][2] = {};
#pragma unroll 16
    for (int f = 0; f < 64; f++) {
        float4 zz = *reinterpret_cast<const float4*>(pbase + f * LDT);
        float4 ww = *reinterpret_cast<const float4*>(kbase + f * LDT);
        u64 b01 = pk2(ww.x, ww.y), b23 = pk2(ww.z, ww.w);
        u64 d;
        d = dup2(zz.x); fma2(acc[0][0], d, b01); fma2(acc[0][1], d, b23);
        d = dup2(zz.y); fma2(acc[1][0], d, b01); fma2(acc[1][1], d, b23);
        d = dup2(zz.z); fma2(acc[2][0], d, b01); fma2(acc[2][1], d, b23);
        d = dup2(zz.w); fma2(acc[3][0], d, b01); fma2(acc[3][1], d, b23);
    }
    float4 bbv = *reinterpret_cast<const float4*>(&b3[4 * tx]);
#pragma unroll
    for (int r = 0; r < 4; r++) {
        float2 lo = up2(acc[r][0]), hi = up2(acc[r][1]);
        float4 res = make_float4(fmaxf(lo.x + bbv.x, 0.f),
                                 fmaxf(lo.y + bbv.y, 0.f),
                                 fmaxf(hi.x + bbv.z, 0.f),
                                 fmaxf(hi.y + bbv.w, 0.f));
        *reinterpret_cast<float4*>(
            &out[((size_t)batch * NTOK + m0 + 4 * ty + r) * 64 + 4 * tx]) = res;
    }
}

// ----------------------------------------------------------------------------
extern "C" void kernel_launch(void* const* d_in, const int* in_sizes, int n_in,
                              void* d_out, int out_size) {
    (void)in_sizes; (void)n_in; (void)out_size;
    const float* x  = (const float*)d_in[0];
    const float* W1 = (const float*)d_in[1];
    const float* b1 = (const float*)d_in[2];
    const float* W2 = (const float*)d_in[3];
    const float* b2 = (const float*)d_in[4];
    const float* W3 = (const float*)d_in[5];
    const float* b3 = (const float*)d_in[6];
    float* out = (float*)d_out;

    constexpr int P_SMEM     = (4 * 64 * LDT + 64) * (int)sizeof(float); // 69888
    constexpr int FLASH_SMEM = 4 * 64 * LDT * (int)sizeof(float);        // 69632
    static bool attr_done = false;
    if (!attr_done) {
        cudaFuncSetAttribute(p_kernel,
                             cudaFuncAttributeMaxDynamicSharedMemorySize, P_SMEM);
        cudaFuncSetAttribute(flash_kernel,
                             cudaFuncAttributeMaxDynamicSharedMemorySize, FLASH_SMEM);
        attr_done = true;
    }

    p_kernel<<<BATCH * NTOK / 64, 256, P_SMEM>>>(x, W1, b1, W2, b2);
    flash_kernel<<<dim3(NTOK / 64, BATCH), 256, FLASH_SMEM>>>(x, W3, b3, out);
}